// round 3
// baseline (speedup 1.0000x reference)
#include <cuda_runtime.h>

#define BB 64
#define SS 2048
#define DD 512
#define UU 256

// Scratch (no allocations allowed): pq_total = q@W2 + b2 + b1, and context partials.
__device__ float g_pq[BB * UU];
__device__ float g_partial[8][BB][DD];

// ---------------------------------------------------------------------------
// Kernel 1: pq_total[b,u] = sum_d query[b,d] * W2[d,u] + b2[u] + b1[u]
// ---------------------------------------------------------------------------
__global__ void pq_kernel(const float* __restrict__ query,
                          const float* __restrict__ W2,
                          const float* __restrict__ b2,
                          const float* __restrict__ b1) {
    int b = blockIdx.x;
    int u = threadIdx.x;  // 256 threads
    __shared__ float q[DD];
    for (int d = threadIdx.x; d < DD; d += blockDim.x) q[d] = query[b * DD + d];
    __syncthreads();
    float acc = b2[u] + b1[u];
#pragma unroll 8
    for (int d = 0; d < DD; d++) acc += q[d] * W2[d * UU + u];
    g_pq[b * UU + u] = acc;
}

// ---------------------------------------------------------------------------
// Kernel 2: score[m] = sum_u tanh( (values@W1)[m,u] + pq_total[b,u] ) * V[u]
// GEMM M=131072, N=256, K=512. Block tile 128(M) x 128(N), K-chunk 8.
// 256 threads, 8x8 per thread (split as 2x 4-row / 4-col groups 64 apart for
// conflict-free float4 LDS). Double-buffered smem: ONE barrier per K-chunk.
// ---------------------------------------------------------------------------
__global__ __launch_bounds__(256, 2) void score_kernel(
    const float* __restrict__ values,
    const float* __restrict__ W1,
    const float* __restrict__ Vw,
    float* __restrict__ score) {
    __shared__ float As[2][8][128];   // [buf][k][m]
    __shared__ float Bs[2][8][128];   // [buf][k][n]

    const int tid = threadIdx.x;
    const int tx = tid & 15;       // n-group selector
    const int ty = tid >> 4;       // m-group selector

    const size_t m0 = (size_t)blockIdx.x * 128;
    const int b = (int)(m0 >> 11);             // 2048 % 128 == 0 -> single b per block
    const float* __restrict__ pq = g_pq + b * UU;

    // A-tile load mapping: thread loads one float4 of values
    const int am  = tid >> 1;            // row 0..127
    const int akg = (tid & 1) * 4;       // k offset 0 or 4
    const float* aptr = values + (m0 + am) * DD + akg;
    // B-tile load mapping
    const int bk = tid >> 5;             // k row 0..7
    const int bc = (tid & 31) * 4;       // n col group

    float sp[8];
#pragma unroll
    for (int i = 0; i < 8; i++) sp[i] = 0.f;

    for (int nc = 0; nc < 2; nc++) {
        const int n0 = nc * 128;
        float acc[8][8];
#pragma unroll
        for (int i = 0; i < 8; i++)
#pragma unroll
            for (int j = 0; j < 8; j++) acc[i][j] = 0.f;

        // load tile 0 into buffer 0
        {
            float4 av = *(const float4*)(aptr);
            float4 bv = *(const float4*)(W1 + (size_t)bk * UU + n0 + bc);
            As[0][akg + 0][am] = av.x;
            As[0][akg + 1][am] = av.y;
            As[0][akg + 2][am] = av.z;
            As[0][akg + 3][am] = av.w;
            *(float4*)&Bs[0][bk][bc] = bv;
        }
        __syncthreads();

        for (int kc = 0; kc < 64; kc++) {
            const int p = kc & 1;
            float4 av, bv;
            if (kc + 1 < 64) {
                av = *(const float4*)(aptr + (kc + 1) * 8);
                bv = *(const float4*)(W1 + (size_t)((kc + 1) * 8 + bk) * UU + n0 + bc);
            }

#pragma unroll
            for (int k = 0; k < 8; k++) {
                float a[8], bbv[8];
                *(float4*)&a[0]   = *(const float4*)&As[p][k][ty * 4];
                *(float4*)&a[4]   = *(const float4*)&As[p][k][64 + ty * 4];
                *(float4*)&bbv[0] = *(const float4*)&Bs[p][k][tx * 4];
                *(float4*)&bbv[4] = *(const float4*)&Bs[p][k][64 + tx * 4];
#pragma unroll
                for (int i = 0; i < 8; i++)
#pragma unroll
                    for (int j = 0; j < 8; j++) acc[i][j] += a[i] * bbv[j];
            }

            if (kc + 1 < 64) {
                const int q = p ^ 1;
                As[q][akg + 0][am] = av.x;
                As[q][akg + 1][am] = av.y;
                As[q][akg + 2][am] = av.z;
                As[q][akg + 3][am] = av.w;
                *(float4*)&Bs[q][bk][bc] = bv;
                __syncthreads();
            }
        }
        if (nc == 0) __syncthreads();  // protect buffers before next nc pass

        // fused epilogue: tanh + dot with V, accumulate per-row partial
#pragma unroll
        for (int j = 0; j < 8; j++) {
            const int ucol = n0 + ((j >> 2) * 64 + tx * 4 + (j & 3));
            const float c  = pq[ucol];
            const float vj = Vw[ucol];
#pragma unroll
            for (int i = 0; i < 8; i++) sp[i] += tanhf(acc[i][j] + c) * vj;
        }
    }

    // reduce sp over the 16 tx lanes (two independent 16-lane halves per warp)
#pragma unroll
    for (int i = 0; i < 8; i++) {
        float v = sp[i];
        v += __shfl_xor_sync(0xffffffffu, v, 1);
        v += __shfl_xor_sync(0xffffffffu, v, 2);
        v += __shfl_xor_sync(0xffffffffu, v, 4);
        v += __shfl_xor_sync(0xffffffffu, v, 8);
        if (tx == 0) {
            const int r = (i >> 2) * 64 + ty * 4 + (i & 3);
            score[m0 + r] = v;
        }
    }
}

// ---------------------------------------------------------------------------
// Kernel 3: in-place softmax over S=2048 per batch row. 64 blocks x 256 thr.
// ---------------------------------------------------------------------------
__global__ void softmax_kernel(float* __restrict__ attn) {
    const int b = blockIdx.x;
    const int t = threadIdx.x;
    __shared__ float red[256];
    float v[8];
    float mx = -1e30f;
#pragma unroll
    for (int i = 0; i < 8; i++) {
        v[i] = attn[b * SS + i * 256 + t];
        mx = fmaxf(mx, v[i]);
    }
    red[t] = mx;
    __syncthreads();
    for (int s = 128; s > 0; s >>= 1) {
        if (t < s) red[t] = fmaxf(red[t], red[t + s]);
        __syncthreads();
    }
    mx = red[0];
    __syncthreads();
    float sum = 0.f;
#pragma unroll
    for (int i = 0; i < 8; i++) {
        v[i] = expf(v[i] - mx);
        sum += v[i];
    }
    red[t] = sum;
    __syncthreads();
    for (int s = 128; s > 0; s >>= 1) {
        if (t < s) red[t] += red[t + s];
        __syncthreads();
    }
    const float inv = 1.f / red[0];
#pragma unroll
    for (int i = 0; i < 8; i++) attn[b * SS + i * 256 + t] = v[i] * inv;
}

// ---------------------------------------------------------------------------
// Kernel 4a: context partials. grid (B, 8 s-chunks), 256 threads.
// thread t accumulates d=t and d=t+256 over its 256-s chunk. Deterministic.
// ---------------------------------------------------------------------------
__global__ __launch_bounds__(256) void ctx_partial(
    const float* __restrict__ values, const float* __restrict__ attn) {
    const int b = blockIdx.x;
    const int sc = blockIdx.y;
    const int t = threadIdx.x;
    __shared__ float a[256];
    a[t] = attn[b * SS + sc * 256 + t];
    __syncthreads();
    const float* vp = values + ((size_t)b * SS + sc * 256) * DD;
    float acc0 = 0.f, acc1 = 0.f;
#pragma unroll 4
    for (int s = 0; s < 256; s++) {
        const float w = a[s];
        acc0 += w * vp[(size_t)s * DD + t];
        acc1 += w * vp[(size_t)s * DD + t + 256];
    }
    g_partial[sc][b][t] = acc0;
    g_partial[sc][b][t + 256] = acc1;
}

// Kernel 4b: reduce the 8 partials.
__global__ void ctx_reduce(float* __restrict__ ctx) {
    const int idx = blockIdx.x * 256 + threadIdx.x;  // 0 .. B*D-1
    const int b = idx / DD, d = idx % DD;
    float s = 0.f;
#pragma unroll
    for (int c = 0; c < 8; c++) s += g_partial[c][b][d];
    ctx[idx] = s;
}

// ---------------------------------------------------------------------------
extern "C" void kernel_launch(void* const* d_in, const int* in_sizes, int n_in,
                              void* d_out, int out_size) {
    const float* query  = (const float*)d_in[0];
    const float* values = (const float*)d_in[1];
    const float* W1     = (const float*)d_in[2];
    const float* b1     = (const float*)d_in[3];
    const float* W2     = (const float*)d_in[4];
    const float* b2     = (const float*)d_in[5];
    const float* Vw     = (const float*)d_in[6];
    // d_in[7] = bV: softmax is shift-invariant, bV cannot affect attn or context.

    float* out  = (float*)d_out;
    float* ctx  = out;            // [B*D] = 32768 floats
    float* attn = out + BB * DD;  // [B*S] = 131072 floats (scores staged here)

    pq_kernel<<<BB, UU>>>(query, W2, b2, b1);
    score_kernel<<<(BB * SS) / 128, 256>>>(values, W1, Vw, attn);
    softmax_kernel<<<BB, 256>>>(attn);
    dim3 g4(BB, 8);
    ctx_partial<<<g4, 256>>>(values, attn);
    ctx_reduce<<<(BB * DD) / 256, 256>>>(ctx);
}

// round 7
// speedup vs baseline: 1.1543x; 1.1543x over previous
#include <cuda_runtime.h>
#include <cstdint>

#define BB 64
#define SS 2048
#define DD 512
#define UU 256

// ---------------- device scratch (no allocations allowed) ------------------
__device__ float g_pq[BB * UU];              // q@W2 + b2 + b1
__device__ float g_spart[4][BB * SS];        // score partials, plane = nc*2 + wn
__device__ float g_partial[16][BB][DD];      // context partials

// ---------------- helpers ---------------------------------------------------
__device__ __forceinline__ uint32_t to_tf32(float x) {
    uint32_t r;
    asm("cvt.rna.tf32.f32 %0, %1;" : "=r"(r) : "f"(x));
    return r;
}
__device__ __forceinline__ void mma_tf32(float* d, const uint32_t* a, const uint32_t* b) {
    asm volatile(
        "mma.sync.aligned.m16n8k8.row.col.f32.tf32.tf32.f32 "
        "{%0,%1,%2,%3}, {%4,%5,%6,%7}, {%8,%9}, {%0,%1,%2,%3};"
        : "+f"(d[0]), "+f"(d[1]), "+f"(d[2]), "+f"(d[3])
        : "r"(a[0]), "r"(a[1]), "r"(a[2]), "r"(a[3]), "r"(b[0]), "r"(b[1]));
}

// ---------------------------------------------------------------------------
// Kernel 1: pq[b,u] = query@W2 + b2 + b1
// ---------------------------------------------------------------------------
__global__ void pq_kernel(const float* __restrict__ query,
                          const float* __restrict__ W2,
                          const float* __restrict__ b2,
                          const float* __restrict__ b1) {
    int b = blockIdx.x;
    int u = threadIdx.x;
    __shared__ float q[DD];
    for (int d = threadIdx.x; d < DD; d += blockDim.x) q[d] = query[b * DD + d];
    __syncthreads();
    float acc = b2[u] + b1[u];
#pragma unroll 8
    for (int d = 0; d < DD; d++) acc += q[d] * W2[d * UU + u];
    g_pq[b * UU + u] = acc;
}

// ---------------------------------------------------------------------------
// Kernel 2: score partials via mma.sync tf32.
// CTA: M=128 x N=128 (N-half nc = blockIdx.x), K=512 in 32 chunks of 16.
// Smem staged directly in MMA fragment layout (conflict-free lds.128/lds.64).
// Warp w: wm=w>>1 (32-row M band), wn=w&1 (64-col N band). acc 2x8x4.
// Each warp writes its OWN partial plane (nc*2+wn) -> no write races.
// ---------------------------------------------------------------------------
__global__ __launch_bounds__(256, 2) void score_tc(
    const float* __restrict__ values,
    const float* __restrict__ W1,
    const float* __restrict__ Vw) {
    __shared__ uint32_t sA[2][2048];   // 2 stages x 16 tiles x 128 words
    __shared__ uint32_t sB[2][2048];   // 2 stages x 16 n-tiles x 128 words
    __shared__ float pq_s[128], V_s[128];

    const int t = threadIdx.x;
    const int nc = blockIdx.x;                 // 0,1 = N-half
    const size_t m0 = (size_t)blockIdx.y * 128;
    const int b = (int)(m0 >> 11);             // batch row (128 | 2048)

    if (t < 128) {
        pq_s[t] = g_pq[b * UU + nc * 128 + t];
        V_s[t] = Vw[nc * 128 + t];
    }

    // ---- producer mappings ----
    const int ar = t >> 1;                // A row 0..127
    const int ac8 = (t & 1) * 8;          // A col base (0 or 8)
    const float* gA = values + (m0 + ar) * DD + ac8;
    const int a_tm = ar >> 4, a_rr = ar & 15;
    const int bk = t >> 4;                // B k-row 0..15
    const int bn8 = (t & 15) * 8;         // B n base
    const float* gB = W1 + (size_t)bk * UU + nc * 128 + bn8;

    // ---- consumer mappings ----
    const int wid = t >> 5, lane = t & 31;
    const int wm = wid >> 1, wn = wid & 1;
    const int g = lane >> 2, tg = lane & 3;

    float acc[2][8][4];
#pragma unroll
    for (int i = 0; i < 2; i++)
#pragma unroll
        for (int j = 0; j < 8; j++)
#pragma unroll
            for (int r = 0; r < 4; r++) acc[i][j][r] = 0.f;

    float ra[8], rb[8];

#define GLOAD(kc) do {                                                        \
        const float* pa_ = gA + (kc) * 16;                                    \
        *(float4*)&ra[0] = *(const float4*)pa_;                               \
        *(float4*)&ra[4] = *(const float4*)(pa_ + 4);                         \
        const float* pb_ = gB + (size_t)(kc) * 16 * UU;                       \
        *(float4*)&rb[0] = *(const float4*)pb_;                               \
        *(float4*)&rb[4] = *(const float4*)(pb_ + 4);                         \
    } while (0)

#define SSTORE(buf) do {                                                      \
        _Pragma("unroll")                                                     \
        for (int j_ = 0; j_ < 8; j_++) {                                      \
            const int c_ = ac8 + j_;                                          \
            const int tk_ = c_ >> 3, cc_ = c_ & 7;                            \
            const int ln_ = (a_rr & 7) * 4 + (cc_ & 3);                       \
            const int rg_ = (a_rr >> 3) + 2 * (cc_ >> 2);                     \
            sA[buf][((a_tm * 2 + tk_) << 7) + ln_ * 4 + rg_] = to_tf32(ra[j_]); \
        }                                                                     \
        _Pragma("unroll")                                                     \
        for (int j_ = 0; j_ < 8; j_++) {                                      \
            const int nl_ = bn8 + j_;                                         \
            const int tn_ = nl_ >> 3, nn_ = nl_ & 7;                          \
            const int ln_ = nn_ * 4 + (bk & 3);                               \
            sB[buf][(tn_ << 7) + ln_ * 4 + (bk >> 2)] = to_tf32(rb[j_]);      \
        }                                                                     \
    } while (0)

    GLOAD(0);
    SSTORE(0);
    __syncthreads();

    for (int kc = 0; kc < 32; kc++) {
        const int p = kc & 1;
        if (kc < 31) GLOAD(kc + 1);

#pragma unroll
        for (int kt = 0; kt < 2; kt++) {
            uint32_t af[2][4];
            *(uint4*)af[0] = *(const uint4*)&sA[p][(((wm * 2 + 0) * 2 + kt) << 7) + lane * 4];
            *(uint4*)af[1] = *(const uint4*)&sA[p][(((wm * 2 + 1) * 2 + kt) << 7) + lane * 4];
            uint32_t bf[8][2];
#pragma unroll
            for (int j = 0; j < 8; j++)
                *(uint2*)bf[j] = *(const uint2*)&sB[p][((wn * 8 + j) << 7) + lane * 4 + kt * 2];
#pragma unroll
            for (int j = 0; j < 8; j++) {
                mma_tf32(acc[0][j], af[0], bf[j]);
                mma_tf32(acc[1][j], af[1], bf[j]);
            }
        }

        if (kc < 31) {
            SSTORE(1 - p);
            __syncthreads();
        }
    }

    // ---- fused epilogue: tanh + V dot, lane-group reduce, write partial ----
    float* plane = g_spart[nc * 2 + wn];
#pragma unroll
    for (int i = 0; i < 2; i++) {
        float p0 = 0.f, p1 = 0.f;
#pragma unroll
        for (int j = 0; j < 8; j++) {
            const int c0 = wn * 64 + j * 8 + 2 * tg;
            const float q0 = pq_s[c0], q1 = pq_s[c0 + 1];
            const float v0 = V_s[c0], v1 = V_s[c0 + 1];
            p0 += tanhf(acc[i][j][0] + q0) * v0 + tanhf(acc[i][j][1] + q1) * v1;
            p1 += tanhf(acc[i][j][2] + q0) * v0 + tanhf(acc[i][j][3] + q1) * v1;
        }
        p0 += __shfl_xor_sync(0xffffffffu, p0, 1);
        p0 += __shfl_xor_sync(0xffffffffu, p0, 2);
        p1 += __shfl_xor_sync(0xffffffffu, p1, 1);
        p1 += __shfl_xor_sync(0xffffffffu, p1, 2);
        if (tg == 0) {
            const size_t row = m0 + wm * 32 + i * 16 + g;
            plane[row] = p0;
            plane[row + 8] = p1;
        }
    }
}

// ---------------------------------------------------------------------------
// Kernel 3: softmax over S=2048 per batch; sums 4 partial planes, writes attn.
// ---------------------------------------------------------------------------
__global__ void softmax_kernel(float* __restrict__ attn) {
    const int b = blockIdx.x;
    const int t = threadIdx.x;
    __shared__ float red[256];
    float v[8];
    float mx = -1e30f;
#pragma unroll
    for (int i = 0; i < 8; i++) {
        const int idx = b * SS + i * 256 + t;
        v[i] = (g_spart[0][idx] + g_spart[1][idx]) +
               (g_spart[2][idx] + g_spart[3][idx]);
        mx = fmaxf(mx, v[i]);
    }
    red[t] = mx;
    __syncthreads();
    for (int s = 128; s > 0; s >>= 1) {
        if (t < s) red[t] = fmaxf(red[t], red[t + s]);
        __syncthreads();
    }
    mx = red[0];
    __syncthreads();
    float sum = 0.f;
#pragma unroll
    for (int i = 0; i < 8; i++) {
        v[i] = expf(v[i] - mx);
        sum += v[i];
    }
    red[t] = sum;
    __syncthreads();
    for (int s = 128; s > 0; s >>= 1) {
        if (t < s) red[t] += red[t + s];
        __syncthreads();
    }
    const float inv = 1.f / red[0];
#pragma unroll
    for (int i = 0; i < 8; i++) attn[b * SS + i * 256 + t] = v[i] * inv;
}

// ---------------------------------------------------------------------------
// Kernel 4a: context partials. grid (B, 16), 128 threads, float4 per thread.
// ---------------------------------------------------------------------------
__global__ __launch_bounds__(128) void ctx_partial(
    const float* __restrict__ values, const float* __restrict__ attn) {
    const int b = blockIdx.x;
    const int sc = blockIdx.y;
    const int t = threadIdx.x;
    __shared__ float a[128];
    a[t] = attn[b * SS + sc * 128 + t];
    __syncthreads();
    const float4* vp = (const float4*)(values + ((size_t)b * SS + (size_t)sc * 128) * DD);
    float4 acc = make_float4(0.f, 0.f, 0.f, 0.f);
#pragma unroll 4
    for (int s = 0; s < 128; s++) {
        const float w = a[s];
        const float4 v = vp[(size_t)s * 128 + t];
        acc.x += w * v.x; acc.y += w * v.y; acc.z += w * v.z; acc.w += w * v.w;
    }
    *(float4*)&g_partial[sc][b][t * 4] = acc;
}

// Kernel 4b: reduce the 16 partials.
__global__ void ctx_reduce(float* __restrict__ ctx) {
    const int idx = blockIdx.x * 256 + threadIdx.x;
    const int b = idx / DD, d = idx % DD;
    float s = 0.f;
#pragma unroll
    for (int c = 0; c < 16; c++) s += g_partial[c][b][d];
    ctx[idx] = s;
}

// ---------------------------------------------------------------------------
extern "C" void kernel_launch(void* const* d_in, const int* in_sizes, int n_in,
                              void* d_out, int out_size) {
    const float* query  = (const float*)d_in[0];
    const float* values = (const float*)d_in[1];
    const float* W1     = (const float*)d_in[2];
    const float* b1     = (const float*)d_in[3];
    const float* W2     = (const float*)d_in[4];
    const float* b2     = (const float*)d_in[5];
    const float* Vw     = (const float*)d_in[6];
    // d_in[7] = bV: softmax is shift-invariant -> cannot affect attn or context.

    float* out  = (float*)d_out;
    float* ctx  = out;            // [B*D]
    float* attn = out + BB * DD;  // [B*S]

    pq_kernel<<<BB, UU>>>(query, W2, b2, b1);
    score_tc<<<dim3(2, (BB * SS) / 128), 256>>>(values, W1, Vw);
    softmax_kernel<<<BB, 256>>>(attn);
    ctx_partial<<<dim3(BB, 16), 128>>>(values, attn);
    ctx_reduce<<<(BB * DD) / 256, 256>>>(ctx);
}

// round 8
// speedup vs baseline: 2.8248x; 2.4471x over previous
#include <cuda_runtime.h>
#include <cuda_fp16.h>
#include <cstdint>

#define BB 64
#define SS 2048
#define DD 512
#define UU 256

// ---------------- device scratch (no allocations allowed) ------------------
__device__ float    g_pq[BB * UU];            // q@W2 + b2 + b1
__device__ uint32_t g_Bfrag[2 * 32 * 1024];   // W1 in fp16 MMA-fragment layout
__device__ float    g_spart[4][BB * SS];      // score partials, plane = nc*2+wn
__device__ float    g_partial[16][BB][DD];    // context partials

// ---------------- helpers ---------------------------------------------------
__device__ __forceinline__ uint32_t smem_u32(const void* p) {
    uint32_t a;
    asm("{ .reg .u64 t; cvta.to.shared.u64 t, %1; cvt.u32.u64 %0, t; }"
        : "=r"(a) : "l"(p));
    return a;
}
__device__ __forceinline__ void cp16(uint32_t dst, const void* src) {
    asm volatile("cp.async.cg.shared.global [%0], [%1], 16;" :: "r"(dst), "l"(src));
}
__device__ __forceinline__ uint32_t pack_h2(float lo, float hi) {
    __half2 h = __floats2half2_rn(lo, hi);   // .x = lo (low 16 bits = lower k)
    return *reinterpret_cast<uint32_t*>(&h);
}
__device__ __forceinline__ void mma_f16(float* d, const uint32_t* a, const uint32_t* b) {
    asm volatile(
        "mma.sync.aligned.m16n8k16.row.col.f32.f16.f16.f32 "
        "{%0,%1,%2,%3}, {%4,%5,%6,%7}, {%8,%9}, {%0,%1,%2,%3};"
        : "+f"(d[0]), "+f"(d[1]), "+f"(d[2]), "+f"(d[3])
        : "r"(a[0]), "r"(a[1]), "r"(a[2]), "r"(a[3]), "r"(b[0]), "r"(b[1]));
}

// ---------------------------------------------------------------------------
// Kernel 1: pq[b,u] = query@W2 + b2 + b1
// ---------------------------------------------------------------------------
__global__ void pq_kernel(const float* __restrict__ query,
                          const float* __restrict__ W2,
                          const float* __restrict__ b2,
                          const float* __restrict__ b1) {
    int b = blockIdx.x;
    int u = threadIdx.x;
    __shared__ float q[DD];
    for (int d = threadIdx.x; d < DD; d += blockDim.x) q[d] = query[b * DD + d];
    __syncthreads();
    float acc = b2[u] + b1[u];
#pragma unroll 8
    for (int d = 0; d < DD; d++) acc += q[d] * W2[d * UU + u];
    g_pq[b * UU + u] = acc;
}

// ---------------------------------------------------------------------------
// Kernel 1b: pack W1 into fp16 m16n8k16 B-fragment layout.
// Word w -> [nc(2)][kc(32)][ntile(16)][lane(32)][kslot(2)]
// b-frag for (lane=4g+tg, kslot): halves = W1[kc*16+kslot*8+2tg +{0,1}][col],
// col = nc*128 + ntile*8 + g.
// ---------------------------------------------------------------------------
__global__ void prep_B(const float* __restrict__ W1) {
    const int w = blockIdx.x * 256 + threadIdx.x;      // 0 .. 65535
    const int nc = w >> 15;
    const int kc = (w >> 10) & 31;
    const int r = w & 1023;
    const int tile = r >> 6, rr = r & 63;
    const int lane = rr >> 1, kslot = rr & 1;
    const int g = lane >> 2, tg = lane & 3;
    const int col = nc * 128 + tile * 8 + g;
    const int row = kc * 16 + kslot * 8 + 2 * tg;
    g_Bfrag[w] = pack_h2(W1[row * UU + col], W1[(row + 1) * UU + col]);
}

// ---------------------------------------------------------------------------
// Kernel 2: score partials via mma.sync fp16 (m16n8k16, fp32 accumulate).
// CTA: M=128 x N=128 (nc = blockIdx.x), K=512 in 32 chunks of 16.
// A: LDG->cvt.f16x2->STS in fragment layout (4 STS/thread/chunk).
// B: single cp.async.16 per thread per chunk from pre-packed g_Bfrag.
// Warp w: wm=w>>1 (32 rows), wn=w&1 (64 cols). acc[2][8][4] fp32.
// Each warp writes its OWN partial plane (nc*2+wn) -> no write races.
// ---------------------------------------------------------------------------
__global__ __launch_bounds__(256, 2) void score_tc(
    const float* __restrict__ values,
    const float* __restrict__ Vw) {
    __shared__ uint32_t sA[2][1024];   // 8 m-tiles x 128 words (fp16 pairs)
    __shared__ uint32_t sB[2][1024];   // 16 n-tiles x 64 words
    __shared__ float pq_s[128], V_s[128];

    const int t = threadIdx.x;
    const int nc = blockIdx.x;                 // 0,1 = N-half
    const size_t m0 = (size_t)blockIdx.y * 128;
    const int b = (int)(m0 >> 11);             // batch row (128 | 2048)

    if (t < 128) {
        pq_s[t] = g_pq[b * UU + nc * 128 + t];
        V_s[t] = Vw[nc * 128 + t];
    }

    // ---- producer mappings (A) ----
    const int ar = t >> 1;                 // A row 0..127
    const int ac8 = (t & 1) * 8;           // A col base (0 or 8)
    const float* gA = values + (m0 + ar) * DD + ac8;
    const int a_tm = ar >> 4;              // m-tile 0..7
    const int arr = ar & 15;
    const int g_o = arr & 7, rslot = arr >> 3;
    // B copy source base (words) for this thread
    const uint32_t* gBbase = g_Bfrag + (size_t)nc * 32 * 1024 + t * 4;
    const uint32_t sB0 = smem_u32(sB);

    // ---- consumer mappings ----
    const int wid = t >> 5, lane = t & 31;
    const int wm = wid >> 1, wn = wid & 1;
    const int g = lane >> 2, tg = lane & 3;

    float acc[2][8][4];
#pragma unroll
    for (int i = 0; i < 2; i++)
#pragma unroll
        for (int j = 0; j < 8; j++)
#pragma unroll
            for (int r = 0; r < 4; r++) acc[i][j][r] = 0.f;

    float ra[8];

#define GLOADA(kc) do {                                                       \
        const float* pa_ = gA + (kc) * 16;                                    \
        *(float4*)&ra[0] = *(const float4*)pa_;                               \
        *(float4*)&ra[4] = *(const float4*)(pa_ + 4);                        \
    } while (0)

#define SSTOREA(buf) do {                                                     \
        _Pragma("unroll")                                                     \
        for (int jp_ = 0; jp_ < 4; jp_++) {                                   \
            const int kw_ = (ac8 >> 1) + jp_;                                 \
            const int tg_ = kw_ & 3, ks_ = kw_ >> 2;                          \
            sA[buf][a_tm * 128 + (g_o * 4 + tg_) * 4 + rslot + 2 * ks_] =     \
                pack_h2(ra[2 * jp_], ra[2 * jp_ + 1]);                        \
        }                                                                     \
    } while (0)

#define CPB(kc, buf) do {                                                     \
        cp16(sB0 + ((buf) * 1024 + t * 4) * 4, gBbase + (size_t)(kc) * 1024); \
        asm volatile("cp.async.commit_group;" ::: "memory");                  \
    } while (0)

    CPB(0, 0);
    GLOADA(0);
    SSTOREA(0);
    asm volatile("cp.async.wait_group 0;" ::: "memory");
    __syncthreads();

    for (int kc = 0; kc < 32; kc++) {
        const int p = kc & 1;
        if (kc < 31) {
            CPB(kc + 1, 1 - p);
            GLOADA(kc + 1);
        }

        uint32_t af[2][4];
        *(uint4*)af[0] = *(const uint4*)&sA[p][(wm * 2 + 0) * 128 + lane * 4];
        *(uint4*)af[1] = *(const uint4*)&sA[p][(wm * 2 + 1) * 128 + lane * 4];
        uint32_t bf[8][2];
#pragma unroll
        for (int j = 0; j < 8; j++)
            *(uint2*)bf[j] = *(const uint2*)&sB[p][(wn * 8 + j) * 64 + lane * 2];
#pragma unroll
        for (int j = 0; j < 8; j++) {
            mma_f16(acc[0][j], af[0], bf[j]);
            mma_f16(acc[1][j], af[1], bf[j]);
        }

        if (kc < 31) {
            SSTOREA(1 - p);
            asm volatile("cp.async.wait_group 0;" ::: "memory");
            __syncthreads();
        }
    }

    // ---- fused epilogue: tanh + V dot, lane-group reduce, write partial ----
    float* plane = g_spart[nc * 2 + wn];
#pragma unroll
    for (int i = 0; i < 2; i++) {
        float p0 = 0.f, p1 = 0.f;
#pragma unroll
        for (int j = 0; j < 8; j++) {
            const int c0 = wn * 64 + j * 8 + 2 * tg;
            const float q0 = pq_s[c0], q1 = pq_s[c0 + 1];
            const float v0 = V_s[c0], v1 = V_s[c0 + 1];
            p0 += tanhf(acc[i][j][0] + q0) * v0 + tanhf(acc[i][j][1] + q1) * v1;
            p1 += tanhf(acc[i][j][2] + q0) * v0 + tanhf(acc[i][j][3] + q1) * v1;
        }
        p0 += __shfl_xor_sync(0xffffffffu, p0, 1);
        p0 += __shfl_xor_sync(0xffffffffu, p0, 2);
        p1 += __shfl_xor_sync(0xffffffffu, p1, 1);
        p1 += __shfl_xor_sync(0xffffffffu, p1, 2);
        if (tg == 0) {
            const size_t row = m0 + wm * 32 + i * 16 + g;
            plane[row] = p0;
            plane[row + 8] = p1;
        }
    }
}

// ---------------------------------------------------------------------------
// Kernel 3: softmax over S=2048 per batch; sums 4 partial planes, writes attn.
// ---------------------------------------------------------------------------
__global__ void softmax_kernel(float* __restrict__ attn) {
    const int b = blockIdx.x;
    const int t = threadIdx.x;
    __shared__ float red[256];
    float v[8];
    float mx = -1e30f;
#pragma unroll
    for (int i = 0; i < 8; i++) {
        const int idx = b * SS + i * 256 + t;
        v[i] = (g_spart[0][idx] + g_spart[1][idx]) +
               (g_spart[2][idx] + g_spart[3][idx]);
        mx = fmaxf(mx, v[i]);
    }
    red[t] = mx;
    __syncthreads();
    for (int s = 128; s > 0; s >>= 1) {
        if (t < s) red[t] = fmaxf(red[t], red[t + s]);
        __syncthreads();
    }
    mx = red[0];
    __syncthreads();
    float sum = 0.f;
#pragma unroll
    for (int i = 0; i < 8; i++) {
        v[i] = expf(v[i] - mx);
        sum += v[i];
    }
    red[t] = sum;
    __syncthreads();
    for (int s = 128; s > 0; s >>= 1) {
        if (t < s) red[t] += red[t + s];
        __syncthreads();
    }
    const float inv = 1.f / red[0];
#pragma unroll
    for (int i = 0; i < 8; i++) attn[b * SS + i * 256 + t] = v[i] * inv;
}

// ---------------------------------------------------------------------------
// Kernel 4a: context partials. grid (B, 16), 128 threads, float4 per thread.
// ---------------------------------------------------------------------------
__global__ __launch_bounds__(128) void ctx_partial(
    const float* __restrict__ values, const float* __restrict__ attn) {
    const int b = blockIdx.x;
    const int sc = blockIdx.y;
    const int t = threadIdx.x;
    __shared__ float a[128];
    a[t] = attn[b * SS + sc * 128 + t];
    __syncthreads();
    const float4* vp = (const float4*)(values + ((size_t)b * SS + (size_t)sc * 128) * DD);
    float4 acc = make_float4(0.f, 0.f, 0.f, 0.f);
#pragma unroll 4
    for (int s = 0; s < 128; s++) {
        const float w = a[s];
        const float4 v = vp[(size_t)s * 128 + t];
        acc.x += w * v.x; acc.y += w * v.y; acc.z += w * v.z; acc.w += w * v.w;
    }
    *(float4*)&g_partial[sc][b][t * 4] = acc;
}

// Kernel 4b: reduce the 16 partials.
__global__ void ctx_reduce(float* __restrict__ ctx) {
    const int idx = blockIdx.x * 256 + threadIdx.x;
    const int b = idx / DD, d = idx % DD;
    float s = 0.f;
#pragma unroll
    for (int c = 0; c < 16; c++) s += g_partial[c][b][d];
    ctx[idx] = s;
}

// ---------------------------------------------------------------------------
extern "C" void kernel_launch(void* const* d_in, const int* in_sizes, int n_in,
                              void* d_out, int out_size) {
    const float* query  = (const float*)d_in[0];
    const float* values = (const float*)d_in[1];
    const float* W1     = (const float*)d_in[2];
    const float* b1     = (const float*)d_in[3];
    const float* W2     = (const float*)d_in[4];
    const float* b2     = (const float*)d_in[5];
    const float* Vw     = (const float*)d_in[6];
    // d_in[7] = bV: softmax is shift-invariant -> cannot affect attn or context.

    float* out  = (float*)d_out;
    float* ctx  = out;            // [B*D]
    float* attn = out + BB * DD;  // [B*S]

    pq_kernel<<<BB, UU>>>(query, W2, b2, b1);
    prep_B<<<256, 256>>>(W1);
    score_tc<<<dim3(2, (BB * SS) / 128), 256>>>(values, Vw);
    softmax_kernel<<<BB, 256>>>(attn);
    ctx_partial<<<dim3(BB, 16), 128>>>(values, attn);
    ctx_reduce<<<(BB * DD) / 256, 256>>>(ctx);
}

// round 10
// speedup vs baseline: 2.9283x; 1.0366x over previous
#include <cuda_runtime.h>
#include <cuda_fp16.h>
#include <cstdint>

#define BB 64
#define SS 2048
#define DD 512
#define UU 256

// ---------------- device scratch (no allocations allowed) ------------------
__device__ float    g_pq[BB * UU];            // q@W2 + b2 + b1
__device__ uint32_t g_Bfrag[2 * 32 * 1024];   // W1 in fp16 MMA-fragment layout
__device__ float    g_spart[4][BB * SS];      // score partials, plane = nc*2+wn
__device__ float    g_partial[32][BB][DD];    // context partials

// ---------------- helpers ---------------------------------------------------
__device__ __forceinline__ uint32_t smem_u32(const void* p) {
    uint32_t a;
    asm("{ .reg .u64 t; cvta.to.shared.u64 t, %1; cvt.u32.u64 %0, t; }"
        : "=r"(a) : "l"(p));
    return a;
}
__device__ __forceinline__ void cp16(uint32_t dst, const void* src) {
    asm volatile("cp.async.cg.shared.global [%0], [%1], 16;" :: "r"(dst), "l"(src));
}
__device__ __forceinline__ uint32_t pack_h2(float lo, float hi) {
    __half2 h = __floats2half2_rn(lo, hi);   // .x = lo (low 16 bits = lower k)
    return *reinterpret_cast<uint32_t*>(&h);
}
// two tanh in one MUFU op (fp16x2 hardware tanh)
__device__ __forceinline__ float2 tanh2(float a, float b) {
    __half2 h = __floats2half2_rn(a, b);
    uint32_t u = *reinterpret_cast<uint32_t*>(&h);
    asm("tanh.approx.f16x2 %0, %0;" : "+r"(u));
    __half2 r = *reinterpret_cast<__half2*>(&u);
    return __half22float2(r);
}
__device__ __forceinline__ void mma_f16(float* d, const uint32_t* a, const uint32_t* b) {
    asm volatile(
        "mma.sync.aligned.m16n8k16.row.col.f32.f16.f16.f32 "
        "{%0,%1,%2,%3}, {%4,%5,%6,%7}, {%8,%9}, {%0,%1,%2,%3};"
        : "+f"(d[0]), "+f"(d[1]), "+f"(d[2]), "+f"(d[3])
        : "r"(a[0]), "r"(a[1]), "r"(a[2]), "r"(a[3]), "r"(b[0]), "r"(b[1]));
}

// ---------------------------------------------------------------------------
// Kernel 1: pq[b,u] = query@W2 + b2 + b1
// ---------------------------------------------------------------------------
__global__ void pq_kernel(const float* __restrict__ query,
                          const float* __restrict__ W2,
                          const float* __restrict__ b2,
                          const float* __restrict__ b1) {
    int b = blockIdx.x;
    int u = threadIdx.x;
    __shared__ float q[DD];
    for (int d = threadIdx.x; d < DD; d += blockDim.x) q[d] = query[b * DD + d];
    __syncthreads();
    float acc = b2[u] + b1[u];
#pragma unroll 8
    for (int d = 0; d < DD; d++) acc += q[d] * W2[d * UU + u];
    g_pq[b * UU + u] = acc;
}

// ---------------------------------------------------------------------------
// Kernel 1b: pack W1 into fp16 m16n8k16 B-fragment layout.
// Word w -> [nc(2)][kc(32)][ntile(16)][lane(32)][kslot(2)]
// ---------------------------------------------------------------------------
__global__ void prep_B(const float* __restrict__ W1) {
    const int w = blockIdx.x * 256 + threadIdx.x;      // 0 .. 65535
    const int nc = w >> 15;
    const int kc = (w >> 10) & 31;
    const int r = w & 1023;
    const int tile = r >> 6, rr = r & 63;
    const int lane = rr >> 1, kslot = rr & 1;
    const int g = lane >> 2, tg = lane & 3;
    const int col = nc * 128 + tile * 8 + g;
    const int row = kc * 16 + kslot * 8 + 2 * tg;
    g_Bfrag[w] = pack_h2(W1[row * UU + col], W1[(row + 1) * UU + col]);
}

// ---------------------------------------------------------------------------
// Kernel 2: score partials via mma.sync fp16 (m16n8k16, fp32 accumulate).
// CTA: M=128 x N=128 (nc = blockIdx.x), K=512 in 32 chunks of 16.
// A: LDG->cvt.f16x2->STS in fragment layout. B: one cp.async per thread/chunk.
// Epilogue: fp16x2 hardware tanh (2 per MUFU op) + V dot in fp32.
// Each warp writes its OWN partial plane (nc*2+wn) -> no write races.
// ---------------------------------------------------------------------------
__global__ __launch_bounds__(256, 2) void score_tc(
    const float* __restrict__ values,
    const float* __restrict__ Vw) {
    __shared__ uint32_t sA[2][1024];   // 8 m-tiles x 128 words (fp16 pairs)
    __shared__ uint32_t sB[2][1024];   // 16 n-tiles x 64 words
    __shared__ float pq_s[128], V_s[128];

    const int t = threadIdx.x;
    const int nc = blockIdx.x;                 // 0,1 = N-half
    const size_t m0 = (size_t)blockIdx.y * 128;
    const int b = (int)(m0 >> 11);             // batch row (128 | 2048)

    if (t < 128) {
        pq_s[t] = g_pq[b * UU + nc * 128 + t];
        V_s[t] = Vw[nc * 128 + t];
    }

    // ---- producer mappings (A) ----
    const int ar = t >> 1;                 // A row 0..127
    const int ac8 = (t & 1) * 8;           // A col base (0 or 8)
    const float* gA = values + (m0 + ar) * DD + ac8;
    const int a_tm = ar >> 4;              // m-tile 0..7
    const int arr = ar & 15;
    const int g_o = arr & 7, rslot = arr >> 3;
    // B copy source base (words) for this thread
    const uint32_t* gBbase = g_Bfrag + (size_t)nc * 32 * 1024 + t * 4;
    const uint32_t sB0 = smem_u32(sB);

    // ---- consumer mappings ----
    const int wid = t >> 5, lane = t & 31;
    const int wm = wid >> 1, wn = wid & 1;
    const int g = lane >> 2, tg = lane & 3;

    float acc[2][8][4];
#pragma unroll
    for (int i = 0; i < 2; i++)
#pragma unroll
        for (int j = 0; j < 8; j++)
#pragma unroll
            for (int r = 0; r < 4; r++) acc[i][j][r] = 0.f;

    float ra[8];

#define GLOADA(kc) do {                                                       \
        const float* pa_ = gA + (kc) * 16;                                    \
        *(float4*)&ra[0] = *(const float4*)pa_;                               \
        *(float4*)&ra[4] = *(const float4*)(pa_ + 4);                        \
    } while (0)

#define SSTOREA(buf) do {                                                     \
        _Pragma("unroll")                                                     \
        for (int jp_ = 0; jp_ < 4; jp_++) {                                   \
            const int kw_ = (ac8 >> 1) + jp_;                                 \
            const int tg_ = kw_ & 3, ks_ = kw_ >> 2;                          \
            sA[buf][a_tm * 128 + (g_o * 4 + tg_) * 4 + rslot + 2 * ks_] =     \
                pack_h2(ra[2 * jp_], ra[2 * jp_ + 1]);                        \
        }                                                                     \
    } while (0)

#define CPB(kc, buf) do {                                                     \
        cp16(sB0 + ((buf) * 1024 + t * 4) * 4, gBbase + (size_t)(kc) * 1024); \
        asm volatile("cp.async.commit_group;" ::: "memory");                  \
    } while (0)

    CPB(0, 0);
    GLOADA(0);
    SSTOREA(0);
    asm volatile("cp.async.wait_group 0;" ::: "memory");
    __syncthreads();

    for (int kc = 0; kc < 32; kc++) {
        const int p = kc & 1;
        if (kc < 31) {
            CPB(kc + 1, 1 - p);
            GLOADA(kc + 1);
        }

        uint32_t af[2][4];
        *(uint4*)af[0] = *(const uint4*)&sA[p][(wm * 2 + 0) * 128 + lane * 4];
        *(uint4*)af[1] = *(const uint4*)&sA[p][(wm * 2 + 1) * 128 + lane * 4];
        uint32_t bf[8][2];
#pragma unroll
        for (int j = 0; j < 8; j++)
            *(uint2*)bf[j] = *(const uint2*)&sB[p][(wn * 8 + j) * 64 + lane * 2];
#pragma unroll
        for (int j = 0; j < 8; j++) {
            mma_f16(acc[0][j], af[0], bf[j]);
            mma_f16(acc[1][j], af[1], bf[j]);
        }

        if (kc < 31) {
            SSTOREA(1 - p);
            asm volatile("cp.async.wait_group 0;" ::: "memory");
            __syncthreads();
        }
    }

    // ---- fused epilogue: fp16x2 tanh + V dot, lane reduce, write partial ----
    float* plane = g_spart[nc * 2 + wn];
#pragma unroll
    for (int i = 0; i < 2; i++) {
        float p0 = 0.f, p1 = 0.f;
#pragma unroll
        for (int j = 0; j < 8; j++) {
            const int c0 = wn * 64 + j * 8 + 2 * tg;
            const float q0 = pq_s[c0], q1 = pq_s[c0 + 1];
            const float v0 = V_s[c0], v1 = V_s[c0 + 1];
            const float2 t01 = tanh2(acc[i][j][0] + q0, acc[i][j][1] + q1);
            const float2 t23 = tanh2(acc[i][j][2] + q0, acc[i][j][3] + q1);
            p0 += t01.x * v0 + t01.y * v1;
            p1 += t23.x * v0 + t23.y * v1;
        }
        p0 += __shfl_xor_sync(0xffffffffu, p0, 1);
        p0 += __shfl_xor_sync(0xffffffffu, p0, 2);
        p1 += __shfl_xor_sync(0xffffffffu, p1, 1);
        p1 += __shfl_xor_sync(0xffffffffu, p1, 2);
        if (tg == 0) {
            const size_t row = m0 + wm * 32 + i * 16 + g;
            plane[row] = p0;
            plane[row + 8] = p1;
        }
    }
}

// ---------------------------------------------------------------------------
// Kernel 3: softmax over S=2048 per batch; sums 4 partial planes, writes attn.
// ---------------------------------------------------------------------------
__global__ void softmax_kernel(float* __restrict__ attn) {
    const int b = blockIdx.x;
    const int t = threadIdx.x;
    __shared__ float red[256];
    float v[8];
    float mx = -1e30f;
#pragma unroll
    for (int i = 0; i < 8; i++) {
        const int idx = b * SS + i * 256 + t;
        v[i] = (g_spart[0][idx] + g_spart[1][idx]) +
               (g_spart[2][idx] + g_spart[3][idx]);
        mx = fmaxf(mx, v[i]);
    }
    red[t] = mx;
    __syncthreads();
    for (int s = 128; s > 0; s >>= 1) {
        if (t < s) red[t] = fmaxf(red[t], red[t + s]);
        __syncthreads();
    }
    mx = red[0];
    __syncthreads();
    float sum = 0.f;
#pragma unroll
    for (int i = 0; i < 8; i++) {
        v[i] = expf(v[i] - mx);
        sum += v[i];
    }
    red[t] = sum;
    __syncthreads();
    for (int s = 128; s > 0; s >>= 1) {
        if (t < s) red[t] += red[t + s];
        __syncthreads();
    }
    const float inv = 1.f / red[0];
#pragma unroll
    for (int i = 0; i < 8; i++) attn[b * SS + i * 256 + t] = v[i] * inv;
}

// ---------------------------------------------------------------------------
// Kernel 4a: context partials. grid (B, 32), 128 threads, float4 per thread.
// 64-row s-chunks -> 2048 blocks for higher memory-level parallelism.
// ---------------------------------------------------------------------------
__global__ __launch_bounds__(128) void ctx_partial(
    const float* __restrict__ values, const float* __restrict__ attn) {
    const int b = blockIdx.x;
    const int sc = blockIdx.y;
    const int t = threadIdx.x;
    __shared__ float a[64];
    if (t < 64) a[t] = attn[b * SS + sc * 64 + t];
    __syncthreads();
    const float4* vp = (const float4*)(values + ((size_t)b * SS + (size_t)sc * 64) * DD);
    float4 acc = make_float4(0.f, 0.f, 0.f, 0.f);
#pragma unroll 8
    for (int s = 0; s < 64; s++) {
        const float w = a[s];
        const float4 v = vp[(size_t)s * 128 + t];
        acc.x += w * v.x; acc.y += w * v.y; acc.z += w * v.z; acc.w += w * v.w;
    }
    *(float4*)&g_partial[sc][b][t * 4] = acc;
}

// Kernel 4b: reduce the 32 partials.
__global__ void ctx_reduce(float* __restrict__ ctx) {
    const int idx = blockIdx.x * 256 + threadIdx.x;
    const int b = idx / DD, d = idx % DD;
    float s = 0.f;
#pragma unroll
    for (int c = 0; c < 32; c++) s += g_partial[c][b][d];
    ctx[idx] = s;
}

// ---------------------------------------------------------------------------
extern "C" void kernel_launch(void* const* d_in, const int* in_sizes, int n_in,
                              void* d_out, int out_size) {
    const float* query  = (const float*)d_in[0];
    const float* values = (const float*)d_in[1];
    const float* W1     = (const float*)d_in[2];
    const float* b1     = (const float*)d_in[3];
    const float* W2     = (const float*)d_in[4];
    const float* b2     = (const float*)d_in[5];
    const float* Vw     = (const float*)d_in[6];
    // d_in[7] = bV: softmax is shift-invariant -> cannot affect attn or context.

    float* out  = (float*)d_out;
    float* ctx  = out;            // [B*D]
    float* attn = out + BB * DD;  // [B*S]

    pq_kernel<<<BB, UU>>>(query, W2, b2, b1);
    prep_B<<<256, 256>>>(W1);
    score_tc<<<dim3(2, (BB * SS) / 128), 256>>>(values, Vw);
    softmax_kernel<<<BB, 256>>>(attn);
    ctx_partial<<<dim3(BB, 32), 128>>>(values, attn);
    ctx_reduce<<<(BB * DD) / 256, 256>>>(ctx);
}